// round 10
// baseline (speedup 1.0000x reference)
#include <cuda_runtime.h>

// DistPtsTopo via per-cell moments + separable tri factorization + smem offset tile.
//   D_t = alpha_a + beta_b + 2n (G_a . F_b)   (see R8 derivation)
// k_bin accumulates M=(SumR, Sum|r|^2) and n per cell via REDs (no return).
// k_main: one thread per cell; block-cooperative offset tile in smem (LDS instead
// of scattered LDG), 5-instr inner loop, 128-bit smem transpose store.
// inputs: d_in[0] = offset (3,65,65,65) f32, d_in[1] = points (300000,3) f32
// output: (64^3, 48) f32.

#define NN      65
#define NN2     (NN*NN)
#define NN3     (NN*NN*NN)
#define PTS     300000
#define NCELL   (64*64*64)       // 262144
#define MTPB    128
#define PITCH   52               // 48 + 4 pad words: conflict-free 128-bit smem ops
#define TILE_F  (3*2*3*65)       // 1170 floats: offset slab [d][di][j][k]
#define SMEM_F  ((MTPB/32) * 32 * PITCH)   // 6656 floats (>= TILE_F)

// scratch: zero at module load; k_main self-resets after reading.
__device__ float4 g_momA[NCELL];   // (SumRx, SumRy, SumRz, Sum|r|^2)
__device__ float  g_momN[NCELL];   // point count

// ---------------- kernel 1: accumulate per-cell moments (2 pts/thread) ------------
__global__ __launch_bounds__(256) void k_bin(const float* __restrict__ points) {
    int t = blockIdx.x * blockDim.x + threadIdx.x;
    int p0 = 2 * t;
    if (p0 >= PTS) return;

    const float2* pts2 = (const float2*)points;
    float2 a  = __ldg(pts2 + 3 * t + 0);
    float2 b  = __ldg(pts2 + 3 * t + 1);
    float2 c2 = __ldg(pts2 + 3 * t + 2);

    float x[2] = {a.x, b.y};
    float y[2] = {a.y, c2.x};
    float z[2] = {b.x, c2.y};

#pragma unroll
    for (int i = 0; i < 2; i++) {
        int ci = min(max(__float2int_rd(x[i]), 0), NN - 2);
        int cj = min(max(__float2int_rd(y[i]), 0), NN - 2);
        int ck = min(max(__float2int_rd(z[i]), 0), NN - 2);
        int c = (ci * 64 + cj) * 64 + ck;
        float rx = x[i] - (float)ci;
        float ry = y[i] - (float)cj;
        float rz = z[i] - (float)ck;
        float rr = fmaf(rx, rx, fmaf(ry, ry, rz * rz));
        asm volatile("red.global.add.v4.f32 [%0], {%1, %2, %3, %4};"
                     :: "l"(&g_momA[c]), "f"(rx), "f"(ry), "f"(rz), "f"(rr)
                     : "memory");
        asm volatile("red.global.add.f32 [%0], %1;"
                     :: "l"(&g_momN[c]), "f"(1.0f)
                     : "memory");
    }
}

// ---------------- kernel 2: per-cell closed form, one thread per cell -------------
__global__ __launch_bounds__(MTPB, 8) void k_main(
    const float* __restrict__ offset,
    float* __restrict__ out)
{
    __shared__ float s_mem[SMEM_F];   // phase 1: offset tile; phase 2: transpose buf

    int t = blockIdx.x * blockDim.x + threadIdx.x;   // cell id, natural order
    int lane = threadIdx.x & 31;
    int warp = threadIdx.x >> 5;

    // block geometry: 128 cells = ci fixed, cj in {cj0, cj0+1}, full ck range
    int t0  = blockIdx.x * MTPB;
    int ci  = t0 >> 12;
    int cj0 = (t0 >> 6) & 63;

    // ---- phase 1: cooperative load of offset slab [3][2][3][65] ----
    // tile[((d*2+di)*3+j)*65 + k] = offset[d][ci+di][cj0+j][k]
    {
        int i0 = ci * NN2 + cj0 * NN;
        for (int idx = threadIdx.x; idx < TILE_F; idx += MTPB) {
            int row = idx / 65;            // 0..17 = (d*2+di)*3 + j
            int k   = idx - row * 65;
            int j   = row % 3;
            int ddi = row / 3;             // d*2+di
            int di  = ddi & 1;
            int d   = ddi >> 1;
            s_mem[idx] = __ldg(offset + d * NN3 + i0 + (di * NN2 + j * NN) + k);
        }
    }

    float4 M = g_momA[t];
    float  nM = g_momN[t];
    g_momA[t] = make_float4(0.f, 0.f, 0.f, 0.f);     // self-reset for graph replay
    g_momN[t] = 0.f;

    float M2x = -2.f * M.x, M2y = -2.f * M.y, M2z = -2.f * M.z;
    float n2 = 2.f * nM;

    int cjl = (threadIdx.x >> 6) & 1;     // local cj (0/1) within block
    int ck  = t & 63;

    __syncthreads();

    // ---- read 24 corner values from smem tile ----
    // corner (di,dj,dk): tile[((d*2+di)*3 + (cjl+dj))*65 + ck + dk]
    float off[3][8];
#pragma unroll
    for (int d = 0; d < 3; d++) {
#pragma unroll
        for (int di = 0; di < 2; di++)
#pragma unroll
            for (int dj = 0; dj < 2; dj++)
#pragma unroll
                for (int dk = 0; dk < 2; dk++)
                    off[d][di * 4 + dj * 2 + dk] =
                        s_mem[((d * 2 + di) * 3 + (cjl + dj)) * 65 + ck + dk];
    }

    // edges (numpy enumeration order) + per-dim corner-coordinate sums
    const int EA[12] = {0, 0, 0, 1, 1, 2, 2, 3, 4, 4, 5, 6};
    const int EB[12] = {1, 2, 4, 3, 5, 3, 6, 7, 5, 6, 7, 7};
    const int ES[12][3] = {
        {0,0,1},{0,1,0},{1,0,0},{0,1,2},{1,0,2},{0,2,1},
        {1,2,0},{1,2,2},{2,0,1},{2,1,0},{2,1,2},{2,2,1}};

    // F_e[d] = ES_e[d]/6 + (off_A + off_B)/6
    float F[12][3];
#pragma unroll
    for (int e = 0; e < 12; e++)
#pragma unroll
        for (int d = 0; d < 3; d++)
            F[e][d] = fmaf(off[d][EA[e]] + off[d][EB[e]], (1.f / 6.f),
                           (float)ES[e][d] * (1.f / 6.f));

    // beta_b = n|F_b|^2 + F_b . M2   (b = 2..11)
    float beta[12];
#pragma unroll
    for (int b = 2; b < 12; b++) {
        float ff = fmaf(F[b][0], F[b][0], fmaf(F[b][1], F[b][1], F[b][2] * F[b][2]));
        float fd = fmaf(F[b][0], M2x, fmaf(F[b][1], M2y, F[b][2] * M2z));
        beta[b] = fmaf(nM, ff, fd);
    }

    __syncthreads();   // tile reads done; smem becomes transpose buffer

    float* sw = s_mem + warp * (32 * PITCH) + lane * PITCH;
    float d4[4];
    int tt = 0;

#pragma unroll
    for (int a = 1; a <= 7; a++) {
        float Gx = F[0][0] + F[a][0];
        float Gy = F[0][1] + F[a][1];
        float Gz = F[0][2] + F[a][2];
        float gg = fmaf(Gx, Gx, fmaf(Gy, Gy, Gz * Gz));
        float gd = fmaf(Gx, M2x, fmaf(Gy, M2y, Gz * M2z));
        float alpha = fmaf(nM, gg, M.w + gd);
        float Hx = n2 * Gx, Hy = n2 * Gy, Hz = n2 * Gz;
#pragma unroll
        for (int b = a + 1; b < 12; b++) {
            if (a == 7 && b == 11) break;   // 48 tris total (lex-truncated)
            float ab = alpha + beta[b];
            float D = fmaf(Hx, F[b][0], fmaf(Hy, F[b][1], fmaf(Hz, F[b][2], ab)));
            d4[tt & 3] = D;
            if ((tt & 3) == 3)
                *(float4*)(sw + (tt - 3)) = make_float4(d4[0], d4[1], d4[2], d4[3]);
            tt++;
        }
    }
    __syncwarp();

    // drain: warp's 32 rows are consecutive cells -> 6KB contiguous, float4 ops
    const float* swb = s_mem + warp * (32 * PITCH);
    float4* out4 = (float4*)out + (size_t)(blockIdx.x * MTPB + warp * 32) * 12;
#pragma unroll
    for (int j = 0; j < 12; j++) {
        int g4 = 32 * j + lane;          // 0..383 float4s
        int row = g4 / 12;
        int k = g4 - 12 * row;
        out4[g4] = *(const float4*)(swb + row * PITCH + 4 * k);
    }
}

extern "C" void kernel_launch(void* const* d_in, const int* in_sizes, int n_in,
                              void* d_out, int out_size) {
    const float* offset = (const float*)d_in[0];
    const float* points = (const float*)d_in[1];
    float* out = (float*)d_out;

    k_bin<<<(PTS / 2 + 255) / 256, 256>>>(points);
    k_main<<<NCELL / MTPB, MTPB>>>(offset, out);
}

// round 11
// speedup vs baseline: 1.8517x; 1.8517x over previous
#include <cuda_runtime.h>

// DistPtsTopo via per-cell moments + separable tri factorization (R9 structure).
//   s_t = r - T_t,  T_t = F_0 + F_a + F_b,  F_e = ES_e/6 + (off_A(e)+off_B(e))/6
//   D_t = Mw + n|T|^2 - 2 T.M = alpha_a + beta_b + 2n (G_a . F_b),  G_a = F_0+F_a
// k_bin accumulates M=(SumR, Sum|r|^2) and n per cell via REDs (no return).
// k_main: one thread per cell, batched LDG gathers, 5-instr inner loop,
// 128-bit smem transpose store. launch_bounds(128,8) -> 64 regs, 50% occ cap.
// inputs: d_in[0] = offset (3,65,65,65) f32, d_in[1] = points (300000,3) f32
// output: (64^3, 48) f32.

#define NN      65
#define NN2     (NN*NN)
#define NN3     (NN*NN*NN)
#define PTS     300000
#define NCELL   (64*64*64)       // 262144
#define MTPB    128
#define PITCH   52               // 48 + 4 pad words: conflict-free 128-bit smem ops

// scratch: zero at module load; k_main self-resets after reading.
__device__ float4 g_momA[NCELL];   // (SumRx, SumRy, SumRz, Sum|r|^2)
__device__ float  g_momN[NCELL];   // point count

// ---------------- kernel 1: accumulate per-cell moments (2 pts/thread) ------------
__global__ __launch_bounds__(256) void k_bin(const float* __restrict__ points) {
    int t = blockIdx.x * blockDim.x + threadIdx.x;
    int p0 = 2 * t;
    if (p0 >= PTS) return;

    const float2* pts2 = (const float2*)points;
    float2 a  = __ldg(pts2 + 3 * t + 0);
    float2 b  = __ldg(pts2 + 3 * t + 1);
    float2 c2 = __ldg(pts2 + 3 * t + 2);

    float x[2] = {a.x, b.y};
    float y[2] = {a.y, c2.x};
    float z[2] = {b.x, c2.y};

#pragma unroll
    for (int i = 0; i < 2; i++) {
        int ci = min(max(__float2int_rd(x[i]), 0), NN - 2);
        int cj = min(max(__float2int_rd(y[i]), 0), NN - 2);
        int ck = min(max(__float2int_rd(z[i]), 0), NN - 2);
        int c = (ci * 64 + cj) * 64 + ck;
        float rx = x[i] - (float)ci;
        float ry = y[i] - (float)cj;
        float rz = z[i] - (float)ck;
        float rr = fmaf(rx, rx, fmaf(ry, ry, rz * rz));
        asm volatile("red.global.add.v4.f32 [%0], {%1, %2, %3, %4};"
                     :: "l"(&g_momA[c]), "f"(rx), "f"(ry), "f"(rz), "f"(rr)
                     : "memory");
        asm volatile("red.global.add.f32 [%0], %1;"
                     :: "l"(&g_momN[c]), "f"(1.0f)
                     : "memory");
    }
}

// ---------------- kernel 2: per-cell closed form, one thread per cell -------------
__global__ __launch_bounds__(MTPB, 8) void k_main(
    const float* __restrict__ offset,
    float* __restrict__ out)
{
    __shared__ float s_row[MTPB / 32][32 * PITCH];

    int t = blockIdx.x * blockDim.x + threadIdx.x;   // cell id, natural order
    int lane = threadIdx.x & 31;
    int warp = threadIdx.x >> 5;

    float4 M = g_momA[t];
    float  nM = g_momN[t];
    g_momA[t] = make_float4(0.f, 0.f, 0.f, 0.f);     // self-reset for graph replay
    g_momN[t] = 0.f;

    float M2x = -2.f * M.x, M2y = -2.f * M.y, M2z = -2.f * M.z;
    float n2 = 2.f * nM;

    int ci = t >> 12;
    int cj = (t >> 6) & 63;
    int ck = t & 63;

    // gather 24 offsets (batched LDGs, coalesced in ck, L2-resident)
    int base = (ci * NN + cj) * NN + ck;
    const int COFF[8] = {0, 1, NN, NN + 1, NN2, NN2 + 1, NN2 + NN, NN2 + NN + 1};
    float off[3][8];
#pragma unroll
    for (int d = 0; d < 3; d++) {
        const float* o = offset + d * NN3 + base;
#pragma unroll
        for (int k = 0; k < 8; k++) off[d][k] = __ldg(o + COFF[k]);
    }

    // edges (numpy enumeration order) + per-dim corner-coordinate sums
    const int EA[12] = {0, 0, 0, 1, 1, 2, 2, 3, 4, 4, 5, 6};
    const int EB[12] = {1, 2, 4, 3, 5, 3, 6, 7, 5, 6, 7, 7};
    const int ES[12][3] = {
        {0,0,1},{0,1,0},{1,0,0},{0,1,2},{1,0,2},{0,2,1},
        {1,2,0},{1,2,2},{2,0,1},{2,1,0},{2,1,2},{2,2,1}};

    // F_e[d] = ES_e[d]/6 + (off_A + off_B)/6
    float F[12][3];
#pragma unroll
    for (int e = 0; e < 12; e++)
#pragma unroll
        for (int d = 0; d < 3; d++)
            F[e][d] = fmaf(off[d][EA[e]] + off[d][EB[e]], (1.f / 6.f),
                           (float)ES[e][d] * (1.f / 6.f));

    // beta_b = n|F_b|^2 + F_b . M2   (b = 2..11)
    float beta[12];
#pragma unroll
    for (int b = 2; b < 12; b++) {
        float ff = fmaf(F[b][0], F[b][0], fmaf(F[b][1], F[b][1], F[b][2] * F[b][2]));
        float fd = fmaf(F[b][0], M2x, fmaf(F[b][1], M2y, F[b][2] * M2z));
        beta[b] = fmaf(nM, ff, fd);
    }

    float* sw = s_row[warp] + lane * PITCH;
    float4 v;
    int tt = 0;

#pragma unroll
    for (int a = 1; a <= 7; a++) {
        float Gx = F[0][0] + F[a][0];
        float Gy = F[0][1] + F[a][1];
        float Gz = F[0][2] + F[a][2];
        float gg = fmaf(Gx, Gx, fmaf(Gy, Gy, Gz * Gz));
        float gd = fmaf(Gx, M2x, fmaf(Gy, M2y, Gz * M2z));
        float alpha = fmaf(nM, gg, M.w + gd);
        float Hx = n2 * Gx, Hy = n2 * Gy, Hz = n2 * Gz;
#pragma unroll
        for (int b = a + 1; b < 12; b++) {
            if (a == 7 && b == 11) break;   // 48 tris total (lex-truncated)
            float ab = alpha + beta[b];
            float D = fmaf(Hx, F[b][0], fmaf(Hy, F[b][1], fmaf(Hz, F[b][2], ab)));
            int q = tt & 3;
            if (q == 0)      v.x = D;
            else if (q == 1) v.y = D;
            else if (q == 2) v.z = D;
            else {
                v.w = D;
                *(float4*)(sw + (tt - 3)) = v;
            }
            tt++;
        }
    }
    __syncwarp();

    // drain: warp's 32 rows are consecutive cells -> 6KB contiguous, float4 ops
    const float* swb = s_row[warp];
    float4* out4 = (float4*)out + (size_t)(blockIdx.x * MTPB + warp * 32) * 12;
#pragma unroll
    for (int j = 0; j < 12; j++) {
        int g4 = 32 * j + lane;          // 0..383 float4s
        int row = g4 / 12;
        int k = g4 - 12 * row;
        out4[g4] = *(const float4*)(swb + row * PITCH + 4 * k);
    }
}

extern "C" void kernel_launch(void* const* d_in, const int* in_sizes, int n_in,
                              void* d_out, int out_size) {
    const float* offset = (const float*)d_in[0];
    const float* points = (const float*)d_in[1];
    float* out = (float*)d_out;

    k_bin<<<(PTS / 2 + 255) / 256, 256>>>(points);
    k_main<<<NCELL / MTPB, MTPB>>>(offset, out);
}